// round 6
// baseline (speedup 1.0000x reference)
#include <cuda_runtime.h>
#include <cstdint>
#include <cstddef>

#define N_ENT 100000
#define NB    50000
#define RNUM  8
#define ENUM  200000

// ---------------- device scratch (static; no allocation) ----------------
__device__ float g_proj[(size_t)(N_ENT + 128) * 1024];   // [n][r*128+o], padded rows
__device__ float g_C[(size_t)N_ENT * 128];

// ---------------- kernel 1: zero C ----------------
__global__ void k_zero(float* __restrict__ p, int n4) {
    for (int i = blockIdx.x * blockDim.x + threadIdx.x; i < n4; i += gridDim.x * blockDim.x)
        ((float4*)p)[i] = make_float4(0.f, 0.f, 0.f, 0.f);
}

// ---------------- kernel 2: proj = emb @ RK_r  (fp32 SIMT GEMM) ----------------
// CTA tile: 64 (m) x 128 (o), K = 128 in 4 chunks of 32.
// 256 threads as 16x16: thread tile 4m x 8n. acc = 32 regs.
__global__ void __launch_bounds__(256, 1) k_proj(const float* __restrict__ emb,
                                                 const float* __restrict__ rk) {
    __shared__ float As[32][68];    // [kk][m], 272B row stride (16B-aligned)
    __shared__ float Bs[32][132];   // [kk][o], 528B row stride (16B-aligned)
    int tid = threadIdx.x;
    int tm = tid & 15, tn = tid >> 4;
    long m0 = (long)blockIdx.x * 64;
    int r = blockIdx.y;
    const float* Bsrc = rk + (size_t)r * 16384;

    float acc[4][8];
#pragma unroll
    for (int i = 0; i < 4; i++)
#pragma unroll
        for (int j = 0; j < 8; j++) acc[i][j] = 0.f;

    for (int kc = 0; kc < 4; kc++) {
        // A: 64 rows x 32 k  (transposed into As[kk][row])
#pragma unroll
        for (int i = 0; i < 8; i++) {
            int idx = tid + i * 256;          // 0..2047
            int row = idx >> 5, kk = idx & 31;
            long gr = m0 + row;
            float v = (gr < N_ENT) ? emb[gr * 128 + kc * 32 + kk] : 0.f;
            As[kk][row] = v;
        }
        // B: 32 d x 128 o (natural layout), float4
#pragma unroll
        for (int i = 0; i < 4; i++) {
            int idx = tid + i * 256;          // 0..1023
            int d = idx >> 5, o4 = idx & 31;
            float4 v = *(const float4*)(Bsrc + (size_t)(kc * 32 + d) * 128 + o4 * 4);
            *(float4*)&Bs[d][o4 * 4] = v;
        }
        __syncthreads();
#pragma unroll
        for (int kk = 0; kk < 32; kk++) {
            float4 a4 = *(float4*)&As[kk][tm * 4];
            float4 b0 = *(float4*)&Bs[kk][tn * 8];
            float4 b1 = *(float4*)&Bs[kk][tn * 8 + 4];
            float av[4] = {a4.x, a4.y, a4.z, a4.w};
            float bv[8] = {b0.x, b0.y, b0.z, b0.w, b1.x, b1.y, b1.z, b1.w};
#pragma unroll
            for (int i = 0; i < 4; i++)
#pragma unroll
                for (int j = 0; j < 8; j++) acc[i][j] += av[i] * bv[j];
        }
        __syncthreads();
    }
    // store (rows up to 100031 < padded 100128; garbage rows never read)
#pragma unroll
    for (int i = 0; i < 4; i++) {
        long row = m0 + tm * 4 + i;
        float* p = g_proj + (size_t)row * 1024 + r * 128 + tn * 8;
        *(float4*)p       = make_float4(acc[i][0], acc[i][1], acc[i][2], acc[i][3]);
        *(float4*)(p + 4) = make_float4(acc[i][4], acc[i][5], acc[i][6], acc[i][7]);
    }
}

// ---------------- kernel 3: scatter C[src] += val * proj[dst, r-slice] -------
__global__ void __launch_bounds__(256) k_scatter(const int* __restrict__ esrc,
                                                 const int* __restrict__ edst,
                                                 const float* __restrict__ eval) {
    long w = ((long)blockIdx.x * blockDim.x + threadIdx.x) >> 5;
    int lane = threadIdx.x & 31;
    if (w >= (long)RNUM * ENUM) return;
    int s = 0, d = 0; float v = 0.f;
    if (lane == 0) { s = esrc[w]; d = edst[w]; v = eval[w]; }
    s = __shfl_sync(0xFFFFFFFFu, s, 0);
    d = __shfl_sync(0xFFFFFFFFu, d, 0);
    v = __shfl_sync(0xFFFFFFFFu, v, 0);
    int r = (int)(w / ENUM);
    const float4* p = (const float4*)(g_proj + (size_t)d * 1024 + (size_t)r * 128);
    float4 x = p[lane];
    float* q = g_C + (size_t)s * 128 + (size_t)lane * 4;
    atomicAdd(q,     x.x * v);
    atomicAdd(q + 1, x.y * v);
    atomicAdd(q + 2, x.z * v);
    atomicAdd(q + 3, x.w * v);
}

// ---------------- kernel 4: out = sigmoid(he/te @ SK + C[idx]) ---------------
static __device__ __forceinline__ float sigf(float x) {
    return 1.0f / (1.0f + __expf(-x));
}

__global__ void __launch_bounds__(256, 1) k_out(const float* __restrict__ he,
                                                const float* __restrict__ te,
                                                const float* __restrict__ sk,
                                                const int* __restrict__ hidx,
                                                const int* __restrict__ tidx,
                                                float* __restrict__ out) {
    __shared__ float As[32][68];
    __shared__ float Bs[32][132];
    __shared__ int sidx[64];
    int tid = threadIdx.x;
    int tm = tid & 15, tn = tid >> 4;
    bool is_head = (blockIdx.y == 0);
    long b0 = (long)blockIdx.x * 64;
    const float* A = is_head ? he : te;
    const int* idxp = is_head ? hidx : tidx;

    if (tid < 64) {
        long b = b0 + tid;
        sidx[tid] = (b < NB) ? idxp[b] : 0;
    }

    float acc[4][8];
#pragma unroll
    for (int i = 0; i < 4; i++)
#pragma unroll
        for (int j = 0; j < 8; j++) acc[i][j] = 0.f;

    for (int kc = 0; kc < 4; kc++) {
#pragma unroll
        for (int i = 0; i < 8; i++) {
            int idx = tid + i * 256;
            int row = idx >> 5, kk = idx & 31;
            long gr = b0 + row;
            float v = (gr < NB) ? A[gr * 128 + kc * 32 + kk] : 0.f;
            As[kk][row] = v;
        }
#pragma unroll
        for (int i = 0; i < 4; i++) {
            int idx = tid + i * 256;
            int d = idx >> 5, o4 = idx & 31;
            float4 v = *(const float4*)(sk + (size_t)(kc * 32 + d) * 128 + o4 * 4);
            *(float4*)&Bs[d][o4 * 4] = v;
        }
        __syncthreads();
#pragma unroll
        for (int kk = 0; kk < 32; kk++) {
            float4 a4 = *(float4*)&As[kk][tm * 4];
            float4 b0v = *(float4*)&Bs[kk][tn * 8];
            float4 b1v = *(float4*)&Bs[kk][tn * 8 + 4];
            float av[4] = {a4.x, a4.y, a4.z, a4.w};
            float bv[8] = {b0v.x, b0v.y, b0v.z, b0v.w, b1v.x, b1v.y, b1v.z, b1v.w};
#pragma unroll
            for (int i = 0; i < 4; i++)
#pragma unroll
                for (int j = 0; j < 8; j++) acc[i][j] += av[i] * bv[j];
        }
        __syncthreads();
    }

    float* outbase = out + (is_head ? (size_t)0 : (size_t)NB * 128);
#pragma unroll
    for (int i = 0; i < 4; i++) {
        long b = b0 + tm * 4 + i;
        if (b < NB) {
            int gi = sidx[tm * 4 + i];
            const float* crow = g_C + (size_t)gi * 128 + tn * 8;
            float4 c0 = *(const float4*)crow;
            float4 c1 = *(const float4*)(crow + 4);
            float* op = outbase + (size_t)b * 128 + tn * 8;
            *(float4*)op = make_float4(sigf(acc[i][0] + c0.x), sigf(acc[i][1] + c0.y),
                                       sigf(acc[i][2] + c0.z), sigf(acc[i][3] + c0.w));
            *(float4*)(op + 4) = make_float4(sigf(acc[i][4] + c1.x), sigf(acc[i][5] + c1.y),
                                             sigf(acc[i][6] + c1.z), sigf(acc[i][7] + c1.w));
        }
    }
}

// ---------------- launch ----------------
extern "C" void kernel_launch(void* const* d_in, const int* in_sizes, int n_in,
                              void* d_out, int out_size) {
    const float* emb    = (const float*)d_in[0];
    const float* head_e = (const float*)d_in[1];
    const float* tail_e = (const float*)d_in[2];
    const float* rk     = (const float*)d_in[3];
    const float* sk     = (const float*)d_in[4];
    const float* eval   = (const float*)d_in[5];
    const int*   hidx   = (const int*)d_in[6];
    const int*   tidx   = (const int*)d_in[7];
    const int*   esrc   = (const int*)d_in[8];
    const int*   edst   = (const int*)d_in[9];
    float* out = (float*)d_out;

    // zero the scatter target
    float* gC;
    cudaGetSymbolAddress((void**)&gC, g_C);
    k_zero<<<1480, 256>>>(gC, N_ENT * 128 / 4);

    // proj[n][r*128+o] = emb[n,:] @ rk[r]   (1563 m-tiles x 8 relations)
    k_proj<<<dim3(1563, 8), 256>>>(emb, rk);

    // C[src] += val * proj[dst, r-slice]   (1 warp per edge)
    {
        long warps = (long)RNUM * ENUM;
        int blocks = (int)((warps * 32 + 255) / 256);
        k_scatter<<<blocks, 256>>>(esrc, edst, eval);
    }

    // out = sigmoid(he/te @ SK + C[idx])
    k_out<<<dim3(782, 2), 256>>>(head_e, tail_e, sk, hidx, tidx, out);
}

// round 8
// speedup vs baseline: 1.5695x; 1.5695x over previous
#include <cuda_runtime.h>
#include <cuda_bf16.h>
#include <mma.h>
#include <cstdint>
#include <cstddef>

using namespace nvcuda;

#define N_ENT 100000
#define NB    50000
#define RNUM  8
#define ENUM  200000

// ---------------- device scratch (static; no allocation) ----------------
__device__ float g_proj[(size_t)(N_ENT + 128) * 1024];   // [n][r*128+o], padded rows
__device__ float g_C[(size_t)N_ENT * 128];
__device__ __nv_bfloat16 g_emb_hi[(size_t)N_ENT * 128];
__device__ __nv_bfloat16 g_emb_lo[(size_t)N_ENT * 128];
__device__ __nv_bfloat16 g_rk_hi[RNUM * 128 * 128];      // [r][d][o] (native layout)
__device__ __nv_bfloat16 g_rk_lo[RNUM * 128 * 128];

// ---------------- kernel 1: zero C ----------------
__global__ void k_zero(float* __restrict__ p, int n4) {
    for (int i = blockIdx.x * blockDim.x + threadIdx.x; i < n4; i += gridDim.x * blockDim.x)
        ((float4*)p)[i] = make_float4(0.f, 0.f, 0.f, 0.f);
}

// ---------------- kernel 2: fp32 -> bf16 hi/lo split ----------------
__global__ void k_convert(const float* __restrict__ in, __nv_bfloat16* __restrict__ hi,
                          __nv_bfloat16* __restrict__ lo, int n4) {
    int i = blockIdx.x * blockDim.x + threadIdx.x;
    if (i >= n4) return;
    float4 v = ((const float4*)in)[i];
    __nv_bfloat16 h0 = __float2bfloat16_rn(v.x);
    __nv_bfloat16 h1 = __float2bfloat16_rn(v.y);
    __nv_bfloat16 h2 = __float2bfloat16_rn(v.z);
    __nv_bfloat16 h3 = __float2bfloat16_rn(v.w);
    __nv_bfloat162 a, b;
    a.x = h0; a.y = h1; b.x = h2; b.y = h3;
    ((__nv_bfloat162*)hi)[2 * i]     = a;
    ((__nv_bfloat162*)hi)[2 * i + 1] = b;
    a.x = __float2bfloat16_rn(v.x - __bfloat162float(h0));
    a.y = __float2bfloat16_rn(v.y - __bfloat162float(h1));
    b.x = __float2bfloat16_rn(v.z - __bfloat162float(h2));
    b.y = __float2bfloat16_rn(v.w - __bfloat162float(h3));
    ((__nv_bfloat162*)lo)[2 * i]     = a;
    ((__nv_bfloat162*)lo)[2 * i + 1] = b;
}

// ---------------- kernel 3: proj = emb @ RK_r  (bf16 WMMA, 3-pass split) ----
// CTA tile 128(m) x 128(o), K=128 in 4 chunks of 32.
// 8 warps as 4(m) x 2(n); warp tile 32 x 64 (2x4 wmma 16x16 frags).
#define ALD 40     // A smem row stride (bf16 elts): 80B, 16B-aligned, conflict-free
#define BLD 136    // B smem row stride: 272B, 16B-aligned, conflict-free
__global__ void __launch_bounds__(256, 1) k_proj_mma() {
    __shared__ __align__(16) __nv_bfloat16 Ah[128 * ALD];
    __shared__ __align__(16) __nv_bfloat16 Al[128 * ALD];
    __shared__ __align__(16) __nv_bfloat16 Bh[32 * BLD];
    __shared__ __align__(16) __nv_bfloat16 Bl[32 * BLD];

    int tid = threadIdx.x, wid = tid >> 5;
    long m0 = (long)blockIdx.x * 128;
    int r = blockIdx.y;
    int wm = (wid & 3) * 32;         // warp m offset
    int wn = (wid >> 2) * 64;        // warp n offset

    wmma::fragment<wmma::accumulator, 16, 16, 16, float> c00, c01, c02, c03, c10, c11, c12, c13;
    wmma::fill_fragment(c00, 0.f); wmma::fill_fragment(c01, 0.f);
    wmma::fill_fragment(c02, 0.f); wmma::fill_fragment(c03, 0.f);
    wmma::fill_fragment(c10, 0.f); wmma::fill_fragment(c11, 0.f);
    wmma::fill_fragment(c12, 0.f); wmma::fill_fragment(c13, 0.f);

    const __nv_bfloat16* Bsrc_h = g_rk_hi + (size_t)r * 16384;
    const __nv_bfloat16* Bsrc_l = g_rk_lo + (size_t)r * 16384;

    for (int kc = 0; kc < 4; kc++) {
        // A chunk: 128 rows x 32 k (hi+lo), uint4 = 8 bf16
#pragma unroll
        for (int i = 0; i < 2; i++) {
            int idx = tid + i * 256;              // 0..511
            int row = idx >> 2, c = (idx & 3) * 8;
            long gr = m0 + row;
            uint4 vh = make_uint4(0u, 0u, 0u, 0u), vl = vh;
            if (gr < N_ENT) {
                vh = *(const uint4*)(g_emb_hi + gr * 128 + kc * 32 + c);
                vl = *(const uint4*)(g_emb_lo + gr * 128 + kc * 32 + c);
            }
            *(uint4*)(Ah + row * ALD + c) = vh;
            *(uint4*)(Al + row * ALD + c) = vl;
        }
        // B chunk: 32 k x 128 o (hi+lo)
#pragma unroll
        for (int i = 0; i < 2; i++) {
            int idx = tid + i * 256;              // 0..511
            int row = idx >> 4, c = (idx & 15) * 8;
            *(uint4*)(Bh + row * BLD + c) = *(const uint4*)(Bsrc_h + (size_t)(kc * 32 + row) * 128 + c);
            *(uint4*)(Bl + row * BLD + c) = *(const uint4*)(Bsrc_l + (size_t)(kc * 32 + row) * 128 + c);
        }
        __syncthreads();

#pragma unroll
        for (int pass = 0; pass < 3; pass++) {
            const __nv_bfloat16* As = (pass == 1) ? Al : Ah;
            const __nv_bfloat16* Bs = (pass == 2) ? Bl : Bh;
#pragma unroll
            for (int ks = 0; ks < 32; ks += 16) {
                wmma::fragment<wmma::matrix_a, 16, 16, 16, __nv_bfloat16, wmma::row_major> fa0, fa1;
                wmma::fragment<wmma::matrix_b, 16, 16, 16, __nv_bfloat16, wmma::row_major> fb0, fb1, fb2, fb3;
                wmma::load_matrix_sync(fa0, As + (wm +  0) * ALD + ks, ALD);
                wmma::load_matrix_sync(fa1, As + (wm + 16) * ALD + ks, ALD);
                wmma::load_matrix_sync(fb0, Bs + ks * BLD + wn +  0, BLD);
                wmma::load_matrix_sync(fb1, Bs + ks * BLD + wn + 16, BLD);
                wmma::load_matrix_sync(fb2, Bs + ks * BLD + wn + 32, BLD);
                wmma::load_matrix_sync(fb3, Bs + ks * BLD + wn + 48, BLD);
                wmma::mma_sync(c00, fa0, fb0, c00);
                wmma::mma_sync(c01, fa0, fb1, c01);
                wmma::mma_sync(c02, fa0, fb2, c02);
                wmma::mma_sync(c03, fa0, fb3, c03);
                wmma::mma_sync(c10, fa1, fb0, c10);
                wmma::mma_sync(c11, fa1, fb1, c11);
                wmma::mma_sync(c12, fa1, fb2, c12);
                wmma::mma_sync(c13, fa1, fb3, c13);
            }
        }
        __syncthreads();
    }

    // epilogue: direct global stores; padded g_proj rows cover m < 100128
    float* base0 = g_proj + (size_t)(m0 + wm) * 1024 + r * 128 + wn;
    float* base1 = base0 + (size_t)16 * 1024;
    wmma::store_matrix_sync(base0 +  0, c00, 1024, wmma::mem_row_major);
    wmma::store_matrix_sync(base0 + 16, c01, 1024, wmma::mem_row_major);
    wmma::store_matrix_sync(base0 + 32, c02, 1024, wmma::mem_row_major);
    wmma::store_matrix_sync(base0 + 48, c03, 1024, wmma::mem_row_major);
    wmma::store_matrix_sync(base1 +  0, c10, 1024, wmma::mem_row_major);
    wmma::store_matrix_sync(base1 + 16, c11, 1024, wmma::mem_row_major);
    wmma::store_matrix_sync(base1 + 32, c12, 1024, wmma::mem_row_major);
    wmma::store_matrix_sync(base1 + 48, c13, 1024, wmma::mem_row_major);
}

// ---------------- kernel 4: scatter C[src] += val * proj[dst, r-slice] -------
__global__ void __launch_bounds__(256) k_scatter(const int* __restrict__ esrc,
                                                 const int* __restrict__ edst,
                                                 const float* __restrict__ eval) {
    long w = ((long)blockIdx.x * blockDim.x + threadIdx.x) >> 5;
    int lane = threadIdx.x & 31;
    if (w >= (long)RNUM * ENUM) return;
    int s = 0, d = 0; float v = 0.f;
    if (lane == 0) { s = esrc[w]; d = edst[w]; v = eval[w]; }
    s = __shfl_sync(0xFFFFFFFFu, s, 0);
    d = __shfl_sync(0xFFFFFFFFu, d, 0);
    v = __shfl_sync(0xFFFFFFFFu, v, 0);
    int r = (int)(w / ENUM);
    const float4* p = (const float4*)(g_proj + (size_t)d * 1024 + (size_t)r * 128);
    float4 x = p[lane];
    x.x *= v; x.y *= v; x.z *= v; x.w *= v;
    float* q = g_C + (size_t)s * 128 + (size_t)lane * 4;
    asm volatile("red.global.add.v4.f32 [%0], {%1, %2, %3, %4};"
                 :: "l"(q), "f"(x.x), "f"(x.y), "f"(x.z), "f"(x.w) : "memory");
}

// ---------------- kernel 5: out = sigmoid(he/te @ SK + C[idx]) ---------------
static __device__ __forceinline__ float sigf(float x) {
    return 1.0f / (1.0f + __expf(-x));
}

__global__ void __launch_bounds__(256, 1) k_out(const float* __restrict__ he,
                                                const float* __restrict__ te,
                                                const float* __restrict__ sk,
                                                const int* __restrict__ hidx,
                                                const int* __restrict__ tidx,
                                                float* __restrict__ out) {
    __shared__ float As[32][68];
    __shared__ float Bs[32][132];
    __shared__ int sidx[64];
    int tid = threadIdx.x;
    int tm = tid & 15, tn = tid >> 4;
    bool is_head = (blockIdx.y == 0);
    long b0 = (long)blockIdx.x * 64;
    const float* A = is_head ? he : te;
    const int* idxp = is_head ? hidx : tidx;

    if (tid < 64) {
        long b = b0 + tid;
        sidx[tid] = (b < NB) ? idxp[b] : 0;
    }

    float acc[4][8];
#pragma unroll
    for (int i = 0; i < 4; i++)
#pragma unroll
        for (int j = 0; j < 8; j++) acc[i][j] = 0.f;

    for (int kc = 0; kc < 4; kc++) {
#pragma unroll
        for (int i = 0; i < 8; i++) {
            int idx = tid + i * 256;
            int row = idx >> 5, kk = idx & 31;
            long gr = b0 + row;
            float v = (gr < NB) ? A[gr * 128 + kc * 32 + kk] : 0.f;
            As[kk][row] = v;
        }
#pragma unroll
        for (int i = 0; i < 4; i++) {
            int idx = tid + i * 256;
            int d = idx >> 5, o4 = idx & 31;
            float4 v = *(const float4*)(sk + (size_t)(kc * 32 + d) * 128 + o4 * 4);
            *(float4*)&Bs[d][o4 * 4] = v;
        }
        __syncthreads();
#pragma unroll
        for (int kk = 0; kk < 32; kk++) {
            float4 a4 = *(float4*)&As[kk][tm * 4];
            float4 b0v = *(float4*)&Bs[kk][tn * 8];
            float4 b1v = *(float4*)&Bs[kk][tn * 8 + 4];
            float av[4] = {a4.x, a4.y, a4.z, a4.w};
            float bv[8] = {b0v.x, b0v.y, b0v.z, b0v.w, b1v.x, b1v.y, b1v.z, b1v.w};
#pragma unroll
            for (int i = 0; i < 4; i++)
#pragma unroll
                for (int j = 0; j < 8; j++) acc[i][j] += av[i] * bv[j];
        }
        __syncthreads();
    }

    float* outbase = out + (is_head ? (size_t)0 : (size_t)NB * 128);
#pragma unroll
    for (int i = 0; i < 4; i++) {
        long b = b0 + tm * 4 + i;
        if (b < NB) {
            int gi = sidx[tm * 4 + i];
            const float* crow = g_C + (size_t)gi * 128 + tn * 8;
            float4 c0 = *(const float4*)crow;
            float4 c1 = *(const float4*)(crow + 4);
            float* op = outbase + (size_t)b * 128 + tn * 8;
            *(float4*)op = make_float4(sigf(acc[i][0] + c0.x), sigf(acc[i][1] + c0.y),
                                       sigf(acc[i][2] + c0.z), sigf(acc[i][3] + c0.w));
            *(float4*)(op + 4) = make_float4(sigf(acc[i][4] + c1.x), sigf(acc[i][5] + c1.y),
                                             sigf(acc[i][6] + c1.z), sigf(acc[i][7] + c1.w));
        }
    }
}

// ---------------- launch ----------------
extern "C" void kernel_launch(void* const* d_in, const int* in_sizes, int n_in,
                              void* d_out, int out_size) {
    const float* emb    = (const float*)d_in[0];
    const float* head_e = (const float*)d_in[1];
    const float* tail_e = (const float*)d_in[2];
    const float* rk     = (const float*)d_in[3];
    const float* sk     = (const float*)d_in[4];
    const float* eval   = (const float*)d_in[5];
    const int*   hidx   = (const int*)d_in[6];
    const int*   tidx   = (const int*)d_in[7];
    const int*   esrc   = (const int*)d_in[8];
    const int*   edst   = (const int*)d_in[9];
    float* out = (float*)d_out;

    float* gC;           cudaGetSymbolAddress((void**)&gC, g_C);
    __nv_bfloat16* eH;   cudaGetSymbolAddress((void**)&eH, g_emb_hi);
    __nv_bfloat16* eL;   cudaGetSymbolAddress((void**)&eL, g_emb_lo);
    __nv_bfloat16* rH;   cudaGetSymbolAddress((void**)&rH, g_rk_hi);
    __nv_bfloat16* rL;   cudaGetSymbolAddress((void**)&rL, g_rk_lo);

    // zero the scatter target
    k_zero<<<1480, 256>>>(gC, N_ENT * 128 / 4);

    // hi/lo bf16 splits (emb + rk, no transpose needed)
    k_convert<<<(N_ENT * 128 / 4 + 255) / 256, 256>>>(emb, eH, eL, N_ENT * 128 / 4);
    k_convert<<<(RNUM * 16384 / 4 + 255) / 256, 256>>>(rk, rH, rL, RNUM * 16384 / 4);

    // proj[n][r*128+o] = emb[n,:] @ rk[r]   (782 m-tiles x 8 relations, WMMA)
    k_proj_mma<<<dim3(782, 8), 256>>>();

    // C[src] += val * proj[dst, r-slice]   (1 warp per edge, red.global v4)
    {
        long warps = (long)RNUM * ENUM;
        int blocks = (int)((warps * 32 + 255) / 256);
        k_scatter<<<blocks, 256>>>(esrc, edst, eval);
    }

    // out = sigmoid(he/te @ SK + C[idx])
    k_out<<<dim3(782, 2), 256>>>(head_e, tail_e, sk, hidx, tidx, out);
}

// round 10
// speedup vs baseline: 1.6000x; 1.0194x over previous
#include <cuda_runtime.h>
#include <cuda_bf16.h>
#include <mma.h>
#include <cstdint>
#include <cstddef>

using namespace nvcuda;

#define N_ENT 100000
#define NB    50000
#define RNUM  8
#define ENUM  200000
#define TPAD  50048   // 391*128, tail scratch row offset

// ---------------- device scratch (static; no allocation) ----------------
__device__ float g_proj[(size_t)(N_ENT + 128) * 1024];   // [n][r*128+o]; later reused as k_out scratch
__device__ float g_C[(size_t)N_ENT * 128];
__device__ __nv_bfloat16 g_emb_hi[(size_t)N_ENT * 128];
__device__ __nv_bfloat16 g_emb_lo[(size_t)N_ENT * 128];
__device__ __nv_bfloat16 g_rk_hi[RNUM * 128 * 128];      // [r][d][o] (native layout)
__device__ __nv_bfloat16 g_rk_lo[RNUM * 128 * 128];
__device__ __nv_bfloat16 g_he_hi[(size_t)NB * 128];
__device__ __nv_bfloat16 g_he_lo[(size_t)NB * 128];
__device__ __nv_bfloat16 g_te_hi[(size_t)NB * 128];
__device__ __nv_bfloat16 g_te_lo[(size_t)NB * 128];
__device__ __nv_bfloat16 g_sk_hi[128 * 128];
__device__ __nv_bfloat16 g_sk_lo[128 * 128];

// ---------------- kernel 1: zero C ----------------
__global__ void k_zero(float* __restrict__ p, int n4) {
    for (int i = blockIdx.x * blockDim.x + threadIdx.x; i < n4; i += gridDim.x * blockDim.x)
        ((float4*)p)[i] = make_float4(0.f, 0.f, 0.f, 0.f);
}

// ---------------- kernel 2: fp32 -> bf16 hi/lo split ----------------
__global__ void k_convert(const float* __restrict__ in, __nv_bfloat16* __restrict__ hi,
                          __nv_bfloat16* __restrict__ lo, int n4) {
    int i = blockIdx.x * blockDim.x + threadIdx.x;
    if (i >= n4) return;
    float4 v = ((const float4*)in)[i];
    __nv_bfloat16 h0 = __float2bfloat16_rn(v.x);
    __nv_bfloat16 h1 = __float2bfloat16_rn(v.y);
    __nv_bfloat16 h2 = __float2bfloat16_rn(v.z);
    __nv_bfloat16 h3 = __float2bfloat16_rn(v.w);
    __nv_bfloat162 a, b;
    a.x = h0; a.y = h1; b.x = h2; b.y = h3;
    ((__nv_bfloat162*)hi)[2 * i]     = a;
    ((__nv_bfloat162*)hi)[2 * i + 1] = b;
    a.x = __float2bfloat16_rn(v.x - __bfloat162float(h0));
    a.y = __float2bfloat16_rn(v.y - __bfloat162float(h1));
    b.x = __float2bfloat16_rn(v.z - __bfloat162float(h2));
    b.y = __float2bfloat16_rn(v.w - __bfloat162float(h3));
    ((__nv_bfloat162*)lo)[2 * i]     = a;
    ((__nv_bfloat162*)lo)[2 * i + 1] = b;
}

// ---------------- WMMA 128x128x128 3-pass split GEMM body ----------------
// 8 warps as 4(m) x 2(n); warp tile 32 x 64 (2x4 wmma 16x16 frags).
#define ALD 40     // A smem row stride (bf16): 80B, 16B-aligned
#define BLD 136    // B smem row stride: 272B, 16B-aligned

// ---------------- kernel 3: proj = emb @ RK_r  (bf16 WMMA, 3-pass split) ----
// grid = dim3(8, 782): x = relation (consecutive bids share the A tile -> L2 reuse)
__global__ void __launch_bounds__(256, 1) k_proj_mma() {
    __shared__ __align__(16) __nv_bfloat16 Ah[128 * ALD];
    __shared__ __align__(16) __nv_bfloat16 Al[128 * ALD];
    __shared__ __align__(16) __nv_bfloat16 Bh[32 * BLD];
    __shared__ __align__(16) __nv_bfloat16 Bl[32 * BLD];

    int tid = threadIdx.x, wid = tid >> 5;
    int r = blockIdx.x;
    long m0 = (long)blockIdx.y * 128;
    int wm = (wid & 3) * 32;
    int wn = (wid >> 2) * 64;

    wmma::fragment<wmma::accumulator, 16, 16, 16, float> c00, c01, c02, c03, c10, c11, c12, c13;
    wmma::fill_fragment(c00, 0.f); wmma::fill_fragment(c01, 0.f);
    wmma::fill_fragment(c02, 0.f); wmma::fill_fragment(c03, 0.f);
    wmma::fill_fragment(c10, 0.f); wmma::fill_fragment(c11, 0.f);
    wmma::fill_fragment(c12, 0.f); wmma::fill_fragment(c13, 0.f);

    const __nv_bfloat16* Bsrc_h = g_rk_hi + (size_t)r * 16384;
    const __nv_bfloat16* Bsrc_l = g_rk_lo + (size_t)r * 16384;

    for (int kc = 0; kc < 4; kc++) {
#pragma unroll
        for (int i = 0; i < 2; i++) {
            int idx = tid + i * 256;
            int row = idx >> 2, c = (idx & 3) * 8;
            long gr = m0 + row;
            uint4 vh = make_uint4(0u, 0u, 0u, 0u), vl = vh;
            if (gr < N_ENT) {
                vh = *(const uint4*)(g_emb_hi + gr * 128 + kc * 32 + c);
                vl = *(const uint4*)(g_emb_lo + gr * 128 + kc * 32 + c);
            }
            *(uint4*)(Ah + row * ALD + c) = vh;
            *(uint4*)(Al + row * ALD + c) = vl;
        }
#pragma unroll
        for (int i = 0; i < 2; i++) {
            int idx = tid + i * 256;
            int row = idx >> 4, c = (idx & 15) * 8;
            *(uint4*)(Bh + row * BLD + c) = *(const uint4*)(Bsrc_h + (size_t)(kc * 32 + row) * 128 + c);
            *(uint4*)(Bl + row * BLD + c) = *(const uint4*)(Bsrc_l + (size_t)(kc * 32 + row) * 128 + c);
        }
        __syncthreads();

#pragma unroll
        for (int pass = 0; pass < 3; pass++) {
            const __nv_bfloat16* As = (pass == 1) ? Al : Ah;
            const __nv_bfloat16* Bs = (pass == 2) ? Bl : Bh;
#pragma unroll
            for (int ks = 0; ks < 32; ks += 16) {
                wmma::fragment<wmma::matrix_a, 16, 16, 16, __nv_bfloat16, wmma::row_major> fa0, fa1;
                wmma::fragment<wmma::matrix_b, 16, 16, 16, __nv_bfloat16, wmma::row_major> fb0, fb1, fb2, fb3;
                wmma::load_matrix_sync(fa0, As + (wm +  0) * ALD + ks, ALD);
                wmma::load_matrix_sync(fa1, As + (wm + 16) * ALD + ks, ALD);
                wmma::load_matrix_sync(fb0, Bs + ks * BLD + wn +  0, BLD);
                wmma::load_matrix_sync(fb1, Bs + ks * BLD + wn + 16, BLD);
                wmma::load_matrix_sync(fb2, Bs + ks * BLD + wn + 32, BLD);
                wmma::load_matrix_sync(fb3, Bs + ks * BLD + wn + 48, BLD);
                wmma::mma_sync(c00, fa0, fb0, c00);
                wmma::mma_sync(c01, fa0, fb1, c01);
                wmma::mma_sync(c02, fa0, fb2, c02);
                wmma::mma_sync(c03, fa0, fb3, c03);
                wmma::mma_sync(c10, fa1, fb0, c10);
                wmma::mma_sync(c11, fa1, fb1, c11);
                wmma::mma_sync(c12, fa1, fb2, c12);
                wmma::mma_sync(c13, fa1, fb3, c13);
            }
        }
        __syncthreads();
    }

    float* base0 = g_proj + (size_t)(m0 + wm) * 1024 + r * 128 + wn;
    float* base1 = base0 + (size_t)16 * 1024;
    wmma::store_matrix_sync(base0 +  0, c00, 1024, wmma::mem_row_major);
    wmma::store_matrix_sync(base0 + 16, c01, 1024, wmma::mem_row_major);
    wmma::store_matrix_sync(base0 + 32, c02, 1024, wmma::mem_row_major);
    wmma::store_matrix_sync(base0 + 48, c03, 1024, wmma::mem_row_major);
    wmma::store_matrix_sync(base1 +  0, c10, 1024, wmma::mem_row_major);
    wmma::store_matrix_sync(base1 + 16, c11, 1024, wmma::mem_row_major);
    wmma::store_matrix_sync(base1 + 32, c12, 1024, wmma::mem_row_major);
    wmma::store_matrix_sync(base1 + 48, c13, 1024, wmma::mem_row_major);
}

// ---------------- kernel 4: scatter C[src] += val * proj[dst, r-slice] -------
__global__ void __launch_bounds__(256) k_scatter(const int* __restrict__ esrc,
                                                 const int* __restrict__ edst,
                                                 const float* __restrict__ eval) {
    long w = ((long)blockIdx.x * blockDim.x + threadIdx.x) >> 5;
    int lane = threadIdx.x & 31;
    if (w >= (long)RNUM * ENUM) return;
    int s = 0, d = 0; float v = 0.f;
    if (lane == 0) { s = esrc[w]; d = edst[w]; v = eval[w]; }
    s = __shfl_sync(0xFFFFFFFFu, s, 0);
    d = __shfl_sync(0xFFFFFFFFu, d, 0);
    v = __shfl_sync(0xFFFFFFFFu, v, 0);
    int r = (int)(w / ENUM);
    const float4* p = (const float4*)(g_proj + (size_t)d * 1024 + (size_t)r * 128);
    float4 x = p[lane];
    x.x *= v; x.y *= v; x.z *= v; x.w *= v;
    float* q = g_C + (size_t)s * 128 + (size_t)lane * 4;
    asm volatile("red.global.add.v4.f32 [%0], {%1, %2, %3, %4};"
                 :: "l"(q), "f"(x.x), "f"(x.y), "f"(x.z), "f"(x.w) : "memory");
}

// ---------------- kernel 5: he/te @ SK (WMMA) into scratch (g_proj reuse) ----
// grid = dim3(391, 2): y=0 head, y=1 tail. Scratch rows: head [0,50048), tail [50048,100096).
__global__ void __launch_bounds__(256, 1) k_out_mma() {
    __shared__ __align__(16) __nv_bfloat16 Ah[128 * ALD];
    __shared__ __align__(16) __nv_bfloat16 Al[128 * ALD];
    __shared__ __align__(16) __nv_bfloat16 Bh[32 * BLD];
    __shared__ __align__(16) __nv_bfloat16 Bl[32 * BLD];

    int tid = threadIdx.x, wid = tid >> 5;
    bool is_head = (blockIdx.y == 0);
    long m0 = (long)blockIdx.x * 128;
    int wm = (wid & 3) * 32;
    int wn = (wid >> 2) * 64;

    const __nv_bfloat16* aH = is_head ? g_he_hi : g_te_hi;
    const __nv_bfloat16* aL = is_head ? g_he_lo : g_te_lo;

    wmma::fragment<wmma::accumulator, 16, 16, 16, float> c00, c01, c02, c03, c10, c11, c12, c13;
    wmma::fill_fragment(c00, 0.f); wmma::fill_fragment(c01, 0.f);
    wmma::fill_fragment(c02, 0.f); wmma::fill_fragment(c03, 0.f);
    wmma::fill_fragment(c10, 0.f); wmma::fill_fragment(c11, 0.f);
    wmma::fill_fragment(c12, 0.f); wmma::fill_fragment(c13, 0.f);

    for (int kc = 0; kc < 4; kc++) {
#pragma unroll
        for (int i = 0; i < 2; i++) {
            int idx = tid + i * 256;
            int row = idx >> 2, c = (idx & 3) * 8;
            long gr = m0 + row;
            uint4 vh = make_uint4(0u, 0u, 0u, 0u), vl = vh;
            if (gr < NB) {
                vh = *(const uint4*)(aH + gr * 128 + kc * 32 + c);
                vl = *(const uint4*)(aL + gr * 128 + kc * 32 + c);
            }
            *(uint4*)(Ah + row * ALD + c) = vh;
            *(uint4*)(Al + row * ALD + c) = vl;
        }
#pragma unroll
        for (int i = 0; i < 2; i++) {
            int idx = tid + i * 256;
            int row = idx >> 4, c = (idx & 15) * 8;
            *(uint4*)(Bh + row * BLD + c) = *(const uint4*)(g_sk_hi + (size_t)(kc * 32 + row) * 128 + c);
            *(uint4*)(Bl + row * BLD + c) = *(const uint4*)(g_sk_lo + (size_t)(kc * 32 + row) * 128 + c);
        }
        __syncthreads();

#pragma unroll
        for (int pass = 0; pass < 3; pass++) {
            const __nv_bfloat16* As = (pass == 1) ? Al : Ah;
            const __nv_bfloat16* Bs = (pass == 2) ? Bl : Bh;
#pragma unroll
            for (int ks = 0; ks < 32; ks += 16) {
                wmma::fragment<wmma::matrix_a, 16, 16, 16, __nv_bfloat16, wmma::row_major> fa0, fa1;
                wmma::fragment<wmma::matrix_b, 16, 16, 16, __nv_bfloat16, wmma::row_major> fb0, fb1, fb2, fb3;
                wmma::load_matrix_sync(fa0, As + (wm +  0) * ALD + ks, ALD);
                wmma::load_matrix_sync(fa1, As + (wm + 16) * ALD + ks, ALD);
                wmma::load_matrix_sync(fb0, Bs + ks * BLD + wn +  0, BLD);
                wmma::load_matrix_sync(fb1, Bs + ks * BLD + wn + 16, BLD);
                wmma::load_matrix_sync(fb2, Bs + ks * BLD + wn + 32, BLD);
                wmma::load_matrix_sync(fb3, Bs + ks * BLD + wn + 48, BLD);
                wmma::mma_sync(c00, fa0, fb0, c00);
                wmma::mma_sync(c01, fa0, fb1, c01);
                wmma::mma_sync(c02, fa0, fb2, c02);
                wmma::mma_sync(c03, fa0, fb3, c03);
                wmma::mma_sync(c10, fa1, fb0, c10);
                wmma::mma_sync(c11, fa1, fb1, c11);
                wmma::mma_sync(c12, fa1, fb2, c12);
                wmma::mma_sync(c13, fa1, fb3, c13);
            }
        }
        __syncthreads();
    }

    size_t rowbase = (is_head ? (size_t)0 : (size_t)TPAD) + m0 + wm;
    float* base0 = g_proj + rowbase * 128 + wn;
    float* base1 = base0 + (size_t)16 * 128;
    wmma::store_matrix_sync(base0 +  0, c00, 128, wmma::mem_row_major);
    wmma::store_matrix_sync(base0 + 16, c01, 128, wmma::mem_row_major);
    wmma::store_matrix_sync(base0 + 32, c02, 128, wmma::mem_row_major);
    wmma::store_matrix_sync(base0 + 48, c03, 128, wmma::mem_row_major);
    wmma::store_matrix_sync(base1 +  0, c10, 128, wmma::mem_row_major);
    wmma::store_matrix_sync(base1 + 16, c11, 128, wmma::mem_row_major);
    wmma::store_matrix_sync(base1 + 32, c12, 128, wmma::mem_row_major);
    wmma::store_matrix_sync(base1 + 48, c13, 128, wmma::mem_row_major);
}

// ---------------- kernel 6: out = sigmoid(scratch + C[idx]) ------------------
static __device__ __forceinline__ float sigf(float x) {
    return 1.0f / (1.0f + __expf(-x));
}

__global__ void __launch_bounds__(256) k_sig(const int* __restrict__ hidx,
                                             const int* __restrict__ tidx,
                                             float* __restrict__ out) {
    long total = (long)2 * NB * 32;
    for (long i = (long)blockIdx.x * blockDim.x + threadIdx.x; i < total;
         i += (long)gridDim.x * blockDim.x) {
        long row = i >> 5;
        int j = (int)(i & 31);
        bool is_head = row < NB;
        long b = is_head ? row : row - NB;
        int gi = is_head ? hidx[b] : tidx[b];
        size_t srow = (is_head ? (size_t)0 : (size_t)TPAD) + b;
        float4 s4 = ((const float4*)g_proj)[srow * 32 + j];
        float4 c4 = ((const float4*)(g_C + (size_t)gi * 128))[j];
        float4 o;
        o.x = sigf(s4.x + c4.x);
        o.y = sigf(s4.y + c4.y);
        o.z = sigf(s4.z + c4.z);
        o.w = sigf(s4.w + c4.w);
        ((float4*)out)[i] = o;
    }
}

// ---------------- launch ----------------
extern "C" void kernel_launch(void* const* d_in, const int* in_sizes, int n_in,
                              void* d_out, int out_size) {
    const float* emb    = (const float*)d_in[0];
    const float* head_e = (const float*)d_in[1];
    const float* tail_e = (const float*)d_in[2];
    const float* rk     = (const float*)d_in[3];
    const float* sk     = (const float*)d_in[4];
    const float* eval   = (const float*)d_in[5];
    const int*   hidx   = (const int*)d_in[6];
    const int*   tidx   = (const int*)d_in[7];
    const int*   esrc   = (const int*)d_in[8];
    const int*   edst   = (const int*)d_in[9];
    float* out = (float*)d_out;

    float* gC;           cudaGetSymbolAddress((void**)&gC, g_C);
    __nv_bfloat16* eH;   cudaGetSymbolAddress((void**)&eH, g_emb_hi);
    __nv_bfloat16* eL;   cudaGetSymbolAddress((void**)&eL, g_emb_lo);
    __nv_bfloat16* rH;   cudaGetSymbolAddress((void**)&rH, g_rk_hi);
    __nv_bfloat16* rL;   cudaGetSymbolAddress((void**)&rL, g_rk_lo);
    __nv_bfloat16* hH;   cudaGetSymbolAddress((void**)&hH, g_he_hi);
    __nv_bfloat16* hL;   cudaGetSymbolAddress((void**)&hL, g_he_lo);
    __nv_bfloat16* tH;   cudaGetSymbolAddress((void**)&tH, g_te_hi);
    __nv_bfloat16* tL;   cudaGetSymbolAddress((void**)&tL, g_te_lo);
    __nv_bfloat16* sH;   cudaGetSymbolAddress((void**)&sH, g_sk_hi);
    __nv_bfloat16* sL;   cudaGetSymbolAddress((void**)&sL, g_sk_lo);

    // zero the scatter target
    k_zero<<<1480, 256>>>(gC, N_ENT * 128 / 4);

    // hi/lo bf16 splits (all operands keep native layout; no transposes)
    k_convert<<<(N_ENT * 128 / 4 + 255) / 256, 256>>>(emb, eH, eL, N_ENT * 128 / 4);
    k_convert<<<(RNUM * 16384 / 4 + 255) / 256, 256>>>(rk, rH, rL, RNUM * 16384 / 4);
    k_convert<<<(NB * 32 + 255) / 256, 256>>>(head_e, hH, hL, NB * 32);
    k_convert<<<(NB * 32 + 255) / 256, 256>>>(tail_e, tH, tL, NB * 32);
    k_convert<<<(16384 / 4 + 255) / 256, 256>>>(sk, sH, sL, 16384 / 4);

    // proj[n][r*128+o] = emb[n,:] @ rk[r]   (x = relation -> A-tile L2 reuse)
    k_proj_mma<<<dim3(8, 782), 256>>>();

    // C[src] += val * proj[dst, r-slice]   (1 warp per edge, red.global v4)
    {
        long warps = (long)RNUM * ENUM;
        int blocks = (int)((warps * 32 + 255) / 256);
        k_scatter<<<blocks, 256>>>(esrc, edst, eval);
    }

    // he/te @ SK -> scratch (reuses g_proj), then fused gather+sigmoid epilogue
    k_out_mma<<<dim3(391, 2), 256>>>();
    k_sig<<<12500, 256>>>(hidx, tidx, out);
}